// round 12
// baseline (speedup 1.0000x reference)
#include <cuda_runtime.h>
#include <stdint.h>

#define LL 401
#define BB 256
#define PLANE 160801             // LL*LL
#define TOTELEM (BB * PLANE)     // 41,165,056 (divisible by 4)
#define PROWS 51                 // rows per panel
#define NPANEL 8
#define NBLK (BB * NPANEL)       // 2048
#define TPB 128
#define RCH 4                    // rows per chunk (= warps per block)
#define BUFN 1616                // floats per buffer (>= 3 + 4*401, 16B mult)

// ---------------- device-global scratch (no allocations allowed) -------------
__device__ double g_bin[LL];
__device__ double g_W;
__device__ double g_NC;
__device__ double g_bSame[BB];
__device__ double g_bNc[BB];
__device__ unsigned char g_P[BB * LL + 64];  // bit0=comp b1=any b2=f b3=r (+pad)
__device__ unsigned g_done;

// ---------------- mbarrier / bulk-copy PTX ----------------------------------
__device__ __forceinline__ unsigned smem_u32(const void* p) {
    return (unsigned)__cvta_generic_to_shared(p);
}
__device__ __forceinline__ void mbar_init(unsigned a, unsigned cnt) {
    asm volatile("mbarrier.init.shared.b64 [%0], %1;" :: "r"(a), "r"(cnt) : "memory");
}
__device__ __forceinline__ void mbar_expect_tx(unsigned a, unsigned tx) {
    asm volatile("mbarrier.arrive.expect_tx.shared.b64 _, [%0], %1;" :: "r"(a), "r"(tx) : "memory");
}
__device__ __forceinline__ void bulk_g2s(unsigned dst, const void* src, unsigned bytes, unsigned mbar) {
    asm volatile("cp.async.bulk.shared::cluster.global.mbarrier::complete_tx::bytes [%0], [%1], %2, [%3];"
                 :: "r"(dst), "l"(src), "r"(bytes), "r"(mbar) : "memory");
}
__device__ __forceinline__ void mbar_wait(unsigned a, unsigned parity) {
    asm volatile("{\n\t.reg .pred P1;\n\t"
                 "WL_%=:\n\t"
                 "mbarrier.try_wait.parity.acquire.cta.shared::cta.b64 P1, [%0], %1, 0x989680;\n\t"
                 "@P1 bra.uni WD_%=;\n\t"
                 "bra.uni WL_%=;\n\t"
                 "WD_%=:\n\t}"
                 :: "r"(a), "r"(parity) : "memory");
}
__device__ __forceinline__ void fence_proxy_async_cta() {
    asm volatile("fence.proxy.async.shared::cta;" ::: "memory");
}

// ---------------- prep: pack bytes + per-batch counts + zero globals ---------
__global__ void k_prep(const float2* __restrict__ logits, const int* __restrict__ ctcf) {
    int b = blockIdx.x, t = threadIdx.x;
    if (b == 0) {
        if (t < LL) g_bin[t] = 0.0;
        if (t == LL) { g_W = 0.0; g_NC = 0.0; }
    }
    __shared__ unsigned char sc[LL];
    __shared__ unsigned long long shw[16];
    unsigned long long pack = 0ull;
    if (t < LL) {
        int idx = b * LL + t;
        float2 l = logits[idx];
        int o = ctcf[idx];
        unsigned c = (l.y > l.x) ? 1u : 0u;
        unsigned A = (o != 0) ? 1u : 0u;
        unsigned F = (o == 1) ? 1u : 0u;
        unsigned R = (o == -1) ? 1u : 0u;
        g_P[idx] = (unsigned char)(c | (A << 1) | (F << 2) | (R << 3));
        sc[t] = (unsigned char)c;
        pack = (unsigned long long)c
             | ((unsigned long long)F << 24)
             | ((unsigned long long)R << 36)
             | ((unsigned long long)A << 48);
    }
    __syncthreads();
    if (t < LL - 1) pack |= ((unsigned long long)(sc[t] == sc[t + 1] ? 1u : 0u)) << 12;

#pragma unroll
    for (int o = 16; o > 0; o >>= 1) pack += __shfl_down_sync(0xffffffffu, pack, o);
    if ((t & 31) == 0) shw[t >> 5] = pack;
    __syncthreads();
    if (t == 0) {
        unsigned long long s = 0;
        for (int w = 0; w < 16; w++) s += shw[w];
        double n1  = (double)(s & 0xFFFull);
        double adj = (double)((s >> 12) & 0xFFFull);
        double F   = (double)((s >> 24) & 0xFFFull);
        double R   = (double)((s >> 36) & 0xFFFull);
        double A   = (double)((s >> 48) & 0xFFFull);
        double n0  = (double)LL - n1;
        g_bSame[b] = n0 * n0 + n1 * n1 - (double)LL - 2.0 * adj;
        g_bNc[b]   = A * A - F * R;
    }
}

// ---------------- block reduction over 128 threads --------------------------
__device__ __forceinline__ double bred128(double v, double* sh) {
    int t = threadIdx.x;
#pragma unroll
    for (int o = 16; o > 0; o >>= 1) v += __shfl_down_sync(0xffffffffu, v, o);
    if ((t & 31) == 0) sh[t >> 5] = v;
    __syncthreads();
    if (t == 0) sh[0] = sh[0] + sh[1] + sh[2] + sh[3];
    __syncthreads();
    double r = sh[0];
    __syncthreads();
    return r;
}

// ---------------- main pass: bulk-copy streaming + diagonal bins -------------
__global__ void __launch_bounds__(TPB, 8) k_main(const float* __restrict__ cm,
                                                 float* __restrict__ out) {
    __shared__ __align__(16) float s_buf[2][BUFN];
    __shared__ float s_bin[RCH][802];
    __shared__ unsigned long long s_mbar[2];
    __shared__ double s_red[4];
    __shared__ double sW[4], sN[4];

    int tid = threadIdx.x;
    int w = tid >> 5, lane = tid & 31;
    int b = blockIdx.x;
    int r0 = blockIdx.y * PROWS;
    int r1 = min(LL, r0 + PROWS);
    int nch = (r1 - r0 + RCH - 1) / RCH;

    unsigned mb0 = smem_u32(&s_mbar[0]);
    unsigned mb1 = smem_u32(&s_mbar[1]);

    // zero bins; init mbarriers
    for (int k = tid; k < RCH * 802; k += TPB) ((float*)s_bin)[k] = 0.f;
    if (tid == 0) { mbar_init(mb0, 1); mbar_init(mb1, 1); fence_proxy_async_cta(); }
    __syncthreads();

    // per-lane cj bytes for this plane: columns lane+32c, c=0..12
    const unsigned char* pb = g_P + b * LL;
    unsigned cjp[4] = {0, 0, 0, 0};
#pragma unroll
    for (int c = 0; c < 13; c++)
        cjp[c >> 2] |= (unsigned)pb[32 * c + lane] << (8 * (c & 3));

    // chunk copy issuer
    auto issue = [&](int c) {
        int i0c = r0 + c * RCH;
        int rows = min(RCH, r1 - i0c);
        long long gstart = (long long)b * PLANE + (long long)i0c * LL;
        long long galign = gstart & ~3ll;
        int off = (int)(gstart - galign);
        int nfl = (off + rows * LL + 3) & ~3;
        if (galign + nfl > (long long)TOTELEM) nfl = (int)((long long)TOTELEM - galign);
        unsigned bytes = (unsigned)nfl * 4u;
        unsigned mb = (c & 1) ? mb1 : mb0;
        mbar_expect_tx(mb, bytes);
        bulk_g2s(smem_u32(&s_buf[c & 1][0]), cm + galign, bytes, mb);
    };

    if (tid == 0) { issue(0); if (nch > 1) issue(1); }

    float accW = 0.f, accNC = 0.f;
    float* mybin = s_bin[w];

    for (int c = 0; c < nch; c++) {
        mbar_wait((c & 1) ? mb1 : mb0, (c >> 1) & 1);

        int i0c = r0 + c * RCH;
        int i = i0c + w;
        if (i < r1) {
            int off = (b + i0c) & 3;                        // (b*PLANE + i0c*401) & 3
            const float* rb = &s_buf[c & 1][off + w * LL];
            unsigned ci = pb[i];

            // per-row masks: wm bit c = same-comp & maskf ; nm bit c = non-conv any-pair
            unsigned cid = ci * 0x01010101u;
            unsigned rselB = (ci & 4u) ? 0x08080808u : 0u;
            unsigned wm = 0, nm = 0;
#pragma unroll
            for (int q = 0; q < 4; q++) {
                unsigned same = ~(cjp[q] ^ cid) & 0x01010101u;
                wm |= (((same * 0x01020408u) >> 24) & 0xFu) << (4 * q);
                unsigned nc_ = (cjp[q] & 0x02020202u) & ~((cjp[q] & rselB) >> 2);
                nm |= (((((nc_ >> 1) & 0x01010101u) * 0x01020408u) >> 24) & 0xFu) << (4 * q);
            }
            nm = (ci & 2u) ? nm : 0u;
#pragma unroll
            for (int dj = -1; dj <= 1; dj++) {              // clear |i-j|<2 from wm
                int t = i + dj - lane;
                if (t >= 0 && (t & 31) == 0) wm &= ~(1u << (t >> 5));
            }

            float* bA = mybin + (i + 400 - lane);
#pragma unroll
            for (int cc = 0; cc < 12; cc++) {
                float vv = rb[32 * cc + lane];
                bA[-32 * cc] += vv;                          // conflict-free RMW
                if ((wm >> cc) & 1u) accW += vv;
                if ((nm >> cc) & 1u) accNC += fmaxf(vv, 0.f);
            }
            if (lane < 17) {                                 // tail chunk c=12
                float vv = rb[384 + lane];
                bA[-384] += vv;
                if ((wm >> 12) & 1u) accW += vv;
                if ((nm >> 12) & 1u) accNC += fmaxf(vv, 0.f);
            }
        }
        __syncthreads();                                     // buffer free
        if (tid == 0 && c + 2 < nch) issue(c + 2);
    }

    // fold per-warp signed-diagonal bins -> g_bin
    __syncthreads();
    for (int t = tid; t < LL; t += TPB) {
        float s = 0.f;
#pragma unroll
        for (int q = 0; q < RCH; q++) {
            s += s_bin[q][400 + t];
            if (t) s += s_bin[q][400 - t];
        }
        atomicAdd(&g_bin[t], (double)s);
    }

    // scalar reductions -> 2 double atomics per block
#pragma unroll
    for (int o = 16; o > 0; o >>= 1) {
        accW  += __shfl_down_sync(0xffffffffu, accW,  o);
        accNC += __shfl_down_sync(0xffffffffu, accNC, o);
    }
    if (lane == 0) { sW[w] = accW; sN[w] = accNC; }
    __syncthreads();
    if (tid == 0) {
        double ww = sW[0] + sW[1] + sW[2] + sW[3];
        double nn = sN[0] + sN[1] + sN[2] + sN[3];
        atomicAdd(&g_W, ww);
        atomicAdd(&g_NC, nn);
    }

    // ---------- last-block-done: fused finalize ----------
    __shared__ bool isLast;
    __threadfence();
    if (tid == 0) {
        unsigned v0 = atomicAdd(&g_done, 1u);
        isLast = (v0 == (unsigned)(NBLK - 1));
    }
    __syncthreads();
    if (!isLast) return;
    if (tid == 0) g_done = 0;
    __threadfence();

    {
        double n = 0, sx = 0, sy = 0, tm = 0, sameC = 0, ncC = 0;
#pragma unroll
        for (int k = 0; k < 4; k++) {
            int t = tid + TPB * k;
            if (t < LL) {
                double bs = g_bin[t];
                double cnt = (t == 0) ? (double)LL : 2.0 * (double)(LL - t);
                double mean = bs / (cnt * (double)BB);
                bool va = (t >= 2) && isfinite(mean) && (mean > 0.0);
                double wv = va ? 1.0 : 0.0;
                double ld = log(fmax((double)t, 1.0));
                double lp = log((va ? mean : 1.0) + 1e-6);
                n += wv; sx += wv * ld; sy += wv * lp;
                if (t >= 2) tm += bs;
            }
            if (t < BB) { sameC += g_bSame[t]; ncC += g_bNc[t]; }
        }
        n = bred128(n, s_red);
        sx = bred128(sx, s_red);
        sy = bred128(sy, s_red);
        tm = bred128(tm, s_red);
        sameC = bred128(sameC, s_red);
        ncC = bred128(ncC, s_red);

        double nsafe = fmax(n, 1.0);
        double xm = sx / nsafe, ym = sy / nsafe;
        double num = 0, den = 0;
#pragma unroll
        for (int k = 0; k < 4; k++) {
            int t = tid + TPB * k;
            if (t < LL) {
                double bs = g_bin[t];
                double cnt = (t == 0) ? (double)LL : 2.0 * (double)(LL - t);
                double mean = bs / (cnt * (double)BB);
                bool va = (t >= 2) && isfinite(mean) && (mean > 0.0);
                double wv = va ? 1.0 : 0.0;
                double ld = log(fmax((double)t, 1.0));
                double lp = log((va ? mean : 1.0) + 1e-6);
                num += wv * (ld - xm) * (lp - ym);
                den += wv * (ld - xm) * (ld - xm);
            }
        }
        num = bred128(num, s_red);
        den = bred128(den, s_red) + 1e-8;

        if (tid == 0) {
            double slope = num / den;
            double dist  = (n >= 5.0) ? (slope + 0.85) * (slope + 0.85) : 0.0;

            double ctcf = (ncC < 1.0) ? 0.0 : g_NC / (ncC + 1e-6);

            double diffC   = (double)BB * ((double)LL * LL - 3.0 * LL + 2.0) - sameC;
            double within  = g_W / fmax(sameC, 1.0);
            double between = (tm - g_W) / fmax(diffC, 1.0);
            double ratio   = within / (fabs(between) + 1e-6);
            double comp    = fmax(0.0, 1.5 - ratio);

            out[0] = (float)dist;
            out[1] = (float)ctcf;
            out[2] = (float)comp;
            out[3] = (float)(dist + 0.5 * ctcf + 0.5 * comp);
        }
    }
}

// ---------------- launch ----------------------------------------------------
extern "C" void kernel_launch(void* const* d_in, const int* in_sizes, int n_in,
                              void* d_out, int out_size) {
    const float* cm      = (const float*)d_in[0];
    const float2* logits = (const float2*)d_in[1];
    const int*   ctcf    = (const int*)d_in[2];
    float* out = (float*)d_out;

    k_prep<<<BB, 512>>>(logits, ctcf);
    k_main<<<dim3(BB, NPANEL), TPB>>>(cm, out);
}